// round 1
// baseline (speedup 1.0000x reference)
#include <cuda_runtime.h>
#include <math.h>

#define BATCH   16
#define SEQ     2048
#define DIM     128
#define BR      64
#define BC      64
#define NTHREADS 512
#define NWARP    16
#define RPW      4          // query rows per warp

#define QS_STRIDE 128
#define KS_STRIDE 132       // padded: lane-indexed row access must be conflict-free
#define VS_STRIDE 128
#define PS_STRIDE 64

#define SMEM_FLOATS (BR*QS_STRIDE + BC*KS_STRIDE + BC*VS_STRIDE + BR*PS_STRIDE)
#define SMEM_BYTES  (SMEM_FLOATS * 4)   // 115712 bytes -> 1 CTA/SM

__global__ __launch_bounds__(NTHREADS, 1)
void fa_fwd_kernel(const float* __restrict__ Qg_, const float* __restrict__ Kg_,
                   const float* __restrict__ Vg_, float* __restrict__ Og_)
{
    extern __shared__ float smem[];
    float* Qs = smem;
    float* Ks = Qs + BR * QS_STRIDE;
    float* Vs = Ks + BC * KS_STRIDE;
    float* Ps = Vs + BC * VS_STRIDE;

    // heavy (large-qt) tiles first to smooth the causal load imbalance
    const int qt   = (int)(gridDim.x - 1u - blockIdx.x);
    const int b    = blockIdx.y;
    const int tid  = threadIdx.x;
    const int warp = tid >> 5;
    const int lane = tid & 31;
    const int r0   = warp * RPW;
    const int c0   = lane << 2;   // output column base (4 per lane)

    const float scale = 0.0883883476483184405f;  // 1/sqrt(128)

    // ---- load Q tile: 64 x 128 floats = 2048 float4, 4 per thread ----
    {
        const float* Qg = Qg_ + ((size_t)b * SEQ + (size_t)qt * BR) * DIM;
        #pragma unroll
        for (int k = 0; k < 4; k++) {
            int idx = tid + k * NTHREADS;        // 0..2047
            int row = idx >> 5;                  // 32 float4 per row
            int c4  = idx & 31;
            *(float4*)&Qs[row * QS_STRIDE + c4 * 4] =
                *((const float4*)(Qg + row * DIM) + c4);
        }
    }

    float m_i[RPW], l_i[RPW];
    float o_acc[RPW][4];
    #pragma unroll
    for (int r = 0; r < RPW; r++) {
        m_i[r] = -INFINITY;
        l_i[r] = 0.0f;
        #pragma unroll
        for (int c = 0; c < 4; c++) o_acc[r][c] = 0.0f;
    }

    for (int kt = 0; kt <= qt; kt++) {
        __syncthreads();   // all warps done reading previous K/V tiles

        // ---- load K,V tiles ----
        {
            const float* Kg = Kg_ + ((size_t)b * SEQ + (size_t)kt * BC) * DIM;
            const float* Vg = Vg_ + ((size_t)b * SEQ + (size_t)kt * BC) * DIM;
            #pragma unroll
            for (int k = 0; k < 4; k++) {
                int idx = tid + k * NTHREADS;
                int row = idx >> 5;
                int c4  = idx & 31;
                *(float4*)&Ks[row * KS_STRIDE + c4 * 4] =
                    *((const float4*)(Kg + row * DIM) + c4);
                *(float4*)&Vs[row * VS_STRIDE + c4 * 4] =
                    *((const float4*)(Vg + row * DIM) + c4);
            }
        }
        __syncthreads();

        // ---- S = Q K^T  (warp: 4 rows x 64 cols; lane cols {lane, lane+32}) ----
        float s[RPW][2];
        #pragma unroll
        for (int r = 0; r < RPW; r++) { s[r][0] = 0.0f; s[r][1] = 0.0f; }

        #pragma unroll 8
        for (int d4 = 0; d4 < 32; d4++) {
            float4 k0 = *(const float4*)&Ks[lane        * KS_STRIDE + d4 * 4];
            float4 k1 = *(const float4*)&Ks[(lane + 32) * KS_STRIDE + d4 * 4];
            #pragma unroll
            for (int r = 0; r < RPW; r++) {
                float4 q = *(const float4*)&Qs[(r0 + r) * QS_STRIDE + d4 * 4];
                s[r][0] += q.x * k0.x; s[r][0] += q.y * k0.y;
                s[r][0] += q.z * k0.z; s[r][0] += q.w * k0.w;
                s[r][1] += q.x * k1.x; s[r][1] += q.y * k1.y;
                s[r][1] += q.z * k1.z; s[r][1] += q.w * k1.w;
            }
        }

        // ---- mask (diag tile only) + online softmax; P is warp-private in smem ----
        const bool diag = (kt == qt);
        #pragma unroll
        for (int r = 0; r < RPW; r++) {
            float s0 = s[r][0] * scale;
            float s1 = s[r][1] * scale;
            if (diag) {
                int i_loc = r0 + r;                 // local row == local col limit
                if (lane      > i_loc) s0 = -1e30f; // exp underflows to exact 0
                if (lane + 32 > i_loc) s1 = -1e30f;
            }
            float mx = fmaxf(s0, s1);
            #pragma unroll
            for (int off = 16; off > 0; off >>= 1)
                mx = fmaxf(mx, __shfl_xor_sync(0xffffffffu, mx, off));
            float m_new = fmaxf(m_i[r], mx);
            float corr  = __expf(m_i[r] - m_new);   // first tile: exp(-inf)=0
            float p0 = __expf(s0 - m_new);
            float p1 = __expf(s1 - m_new);
            float rs = p0 + p1;
            #pragma unroll
            for (int off = 16; off > 0; off >>= 1)
                rs += __shfl_xor_sync(0xffffffffu, rs, off);
            l_i[r] = l_i[r] * corr + rs;
            m_i[r] = m_new;
            #pragma unroll
            for (int c = 0; c < 4; c++) o_acc[r][c] *= corr;
            Ps[(r0 + r) * PS_STRIDE + lane]      = p0;
            Ps[(r0 + r) * PS_STRIDE + lane + 32] = p1;
        }
        __syncwarp();   // P rows are only read by the warp that wrote them

        // ---- O += P V  (lane owns output cols c0..c0+3) ----
        #pragma unroll 4
        for (int t4 = 0; t4 < 16; t4++) {
            float pr[RPW][4];
            #pragma unroll
            for (int r = 0; r < RPW; r++) {
                float4 p4 = *(const float4*)&Ps[(r0 + r) * PS_STRIDE + t4 * 4];
                pr[r][0] = p4.x; pr[r][1] = p4.y; pr[r][2] = p4.z; pr[r][3] = p4.w;
            }
            #pragma unroll
            for (int tt = 0; tt < 4; tt++) {
                float4 v = *(const float4*)&Vs[(t4 * 4 + tt) * VS_STRIDE + c0];
                #pragma unroll
                for (int r = 0; r < RPW; r++) {
                    float p = pr[r][tt];
                    o_acc[r][0] += p * v.x;
                    o_acc[r][1] += p * v.y;
                    o_acc[r][2] += p * v.z;
                    o_acc[r][3] += p * v.w;
                }
            }
        }
    }

    // ---- epilogue: O /= l, store ----
    float* Og = Og_ + ((size_t)b * SEQ + (size_t)qt * BR) * DIM;
    #pragma unroll
    for (int r = 0; r < RPW; r++) {
        float inv = 1.0f / l_i[r];
        float4 o4 = make_float4(o_acc[r][0] * inv, o_acc[r][1] * inv,
                                o_acc[r][2] * inv, o_acc[r][3] * inv);
        *(float4*)&Og[(r0 + r) * DIM + c0] = o4;
    }
}

extern "C" void kernel_launch(void* const* d_in, const int* in_sizes, int n_in,
                              void* d_out, int out_size)
{
    const float* Q = (const float*)d_in[0];
    const float* K = (const float*)d_in[1];
    const float* V = (const float*)d_in[2];
    float* O = (float*)d_out;

    cudaFuncSetAttribute(fa_fwd_kernel,
                         cudaFuncAttributeMaxDynamicSharedMemorySize, SMEM_BYTES);

    dim3 grid(SEQ / BR, BATCH);   // 32 query tiles x 16 batches = 512 CTAs
    fa_fwd_kernel<<<grid, NTHREADS, SMEM_BYTES>>>(Q, K, V, O);
}

// round 3
// speedup vs baseline: 4.5636x; 4.5636x over previous
#include <cuda_runtime.h>
#include <cstdint>
#include <math.h>

#define SEQ  2048
#define DIM  128
#define BR   128
#define BC   64
#define NTHR 256

// smem float strides (mod-32 residues chosen for conflict-free mma fragment access)
#define QF 132   // ≡4 : A-frag loads (4g+tg) conflict-free
#define KF 132   // ≡4 : B-frag loads (4g+tg) conflict-free
#define VF 136   // ≡8 : PV B-frag loads (8tg+g) conflict-free
#define PF 136   // ≡8 : PV A-frag loads (8tg+g) conflict-free (stores 2-way, cheaper side)

// smem float offsets (all ≡0 mod 32 floats)
#define OQ  0
#define OKs (BR*QF)             // 16896
#define OVs (OKs + BC*KF)       // 25344
#define OPs (OVs + BC*VF)       // 34048  (P stored transposed: [t][m])
#define SMEM_FLOATS (OPs + BC*PF)
#define SMEM_BYTES  (SMEM_FLOATS*4)   // 171008 B -> 1 CTA/SM

__device__ __forceinline__ uint32_t tf32_bits(float x){
    uint32_t u; asm("cvt.rna.tf32.f32 %0, %1;" : "=r"(u) : "f"(x)); return u;
}
__device__ __forceinline__ float ex2f(float x){
    float y; asm("ex2.approx.ftz.f32 %0, %1;" : "=f"(y) : "f"(x)); return y;
}
// D = A(16x8,row) * B(8x8,col) + D, tf32 inputs, fp32 accum
__device__ __forceinline__ void mma_tf32(float c[4],
    uint32_t a0, uint32_t a1, uint32_t a2, uint32_t a3, uint32_t b0, uint32_t b1)
{
    asm volatile("mma.sync.aligned.m16n8k8.row.col.f32.tf32.tf32.f32 "
        "{%0,%1,%2,%3}, {%4,%5,%6,%7}, {%8,%9}, {%0,%1,%2,%3};"
        : "+f"(c[0]), "+f"(c[1]), "+f"(c[2]), "+f"(c[3])
        : "r"(a0), "r"(a1), "r"(a2), "r"(a3), "r"(b0), "r"(b1));
}

__global__ __launch_bounds__(NTHR, 1)
void fa_mma_kernel(const float* __restrict__ Qg_, const float* __restrict__ Kg_,
                   const float* __restrict__ Vg_, float* __restrict__ Og_)
{
    extern __shared__ float smf[];
    const int tid  = threadIdx.x;
    const int w    = tid >> 5;
    const int lane = tid & 31;
    const int g    = lane >> 2;   // groupID (row within fragment)
    const int tg   = lane & 3;    // threadID in group (k / col pair)

    // heavy-first scheduling over (qt, b)
    const int qt = 15 - (int)(blockIdx.x >> 4);
    const int b  = (int)(blockIdx.x & 15);
    const int NT = 2 * qt + 2;

    const int rg = w >> 1, cg = w & 1;   // S-phase:  rows rg*32.., cols cg*32..
    const int r2 = w & 3,  c2 = w >> 2;  // PV-phase: rows r2*32.., d-cols c2*64..

    // ---- load Q once: fold scale*log2e, round to tf32 ----
    {
        const float QSC = 0.08838834764831845f * 1.4426950408889634f;
        const float* Qg = Qg_ + ((size_t)b * SEQ + (size_t)qt * BR) * DIM;
        #pragma unroll
        for (int i = 0; i < 16; i++) {
            int idx = tid + i * NTHR;
            int row = idx >> 5, c4 = idx & 31;
            float4 v = *(const float4*)(Qg + row * DIM + c4 * 4);
            uint4 u;
            u.x = tf32_bits(v.x * QSC); u.y = tf32_bits(v.y * QSC);
            u.z = tf32_bits(v.z * QSC); u.w = tf32_bits(v.w * QSC);
            *(uint4*)(smf + OQ + row * QF + c4 * 4) = u;
        }
    }

    float oacc[2][8][4];   // O accum: rows r2*32+mi*16+{g,g+8}, cols c2*64+nj*8+2tg+{0,1}
    float lacc[2][4];      // l accum via ones-column mma (col0 lives at tg==0 lanes)
    #pragma unroll
    for (int mi = 0; mi < 2; mi++) {
        #pragma unroll
        for (int nj = 0; nj < 8; nj++)
            { oacc[mi][nj][0]=0.f; oacc[mi][nj][1]=0.f; oacc[mi][nj][2]=0.f; oacc[mi][nj][3]=0.f; }
        lacc[mi][0]=0.f; lacc[mi][1]=0.f; lacc[mi][2]=0.f; lacc[mi][3]=0.f;
    }

    for (int kt = 0; kt < NT; kt++) {
        __syncthreads();   // prior phase done reading Ks/Vs/Pt

        // ---- load K,V tiles (tf32-rounded) ----
        {
            const float* Kg = Kg_ + ((size_t)b * SEQ + (size_t)kt * BC) * DIM;
            const float* Vg = Vg_ + ((size_t)b * SEQ + (size_t)kt * BC) * DIM;
            #pragma unroll
            for (int i = 0; i < 8; i++) {
                int idx = tid + i * NTHR;
                int t = idx >> 5, c4 = idx & 31;
                float4 kv = *(const float4*)(Kg + t * DIM + c4 * 4);
                float4 vv = *(const float4*)(Vg + t * DIM + c4 * 4);
                uint4 ku, vu;
                ku.x = tf32_bits(kv.x); ku.y = tf32_bits(kv.y);
                ku.z = tf32_bits(kv.z); ku.w = tf32_bits(kv.w);
                vu.x = tf32_bits(vv.x); vu.y = tf32_bits(vv.y);
                vu.z = tf32_bits(vv.z); vu.w = tf32_bits(vv.w);
                *(uint4*)(smf + OKs + t * KF + c4 * 4) = ku;
                *(uint4*)(smf + OVs + t * VF + c4 * 4) = vu;
            }
        }
        __syncthreads();

        // ---- S = Q K^T : warp tile 32 rows x 32 cols, k=128 (16 steps) ----
        float sacc[2][4][4];
        #pragma unroll
        for (int mi = 0; mi < 2; mi++)
            #pragma unroll
            for (int nj = 0; nj < 4; nj++)
                { sacc[mi][nj][0]=0.f; sacc[mi][nj][1]=0.f; sacc[mi][nj][2]=0.f; sacc[mi][nj][3]=0.f; }

        #pragma unroll
        for (int ks = 0; ks < 16; ks++) {
            uint32_t a[2][4];
            #pragma unroll
            for (int mi = 0; mi < 2; mi++) {
                const float* q = smf + OQ + (rg*32 + mi*16 + g) * QF + ks*8;
                a[mi][0] = __float_as_uint(q[tg]);
                a[mi][1] = __float_as_uint(q[8*QF + tg]);
                a[mi][2] = __float_as_uint(q[tg + 4]);
                a[mi][3] = __float_as_uint(q[8*QF + tg + 4]);
            }
            #pragma unroll
            for (int nj = 0; nj < 4; nj++) {
                const float* kk = smf + OKs + (cg*32 + nj*8 + g) * KF + ks*8;
                uint32_t b0 = __float_as_uint(kk[tg]);
                uint32_t b1 = __float_as_uint(kk[tg + 4]);
                mma_tf32(sacc[0][nj], a[0][0],a[0][1],a[0][2],a[0][3], b0, b1);
                mma_tf32(sacc[1][nj], a[1][0],a[1][1],a[1][2],a[1][3], b0, b1);
            }
        }

        // ---- exp2 + causal mask, store P transposed [t][m] ----
        {
            const int rgl = qt*BR + rg*32 + g;     // + mi*16 (+8)
            #pragma unroll
            for (int mi = 0; mi < 2; mi++) {
                const int rglob = rgl + mi*16;
                const int prow  = rg*32 + mi*16 + g;
                #pragma unroll
                for (int nj = 0; nj < 4; nj++) {
                    const int colb = kt*BC + cg*32 + nj*8 + 2*tg;
                    const int pcol = cg*32 + nj*8 + 2*tg;
                    float p0 = ex2f(sacc[mi][nj][0]);
                    float p1 = ex2f(sacc[mi][nj][1]);
                    float p2 = ex2f(sacc[mi][nj][2]);
                    float p3 = ex2f(sacc[mi][nj][3]);
                    p0 = (colb     <= rglob    ) ? __uint_as_float(tf32_bits(p0)) : 0.f;
                    p1 = (colb + 1 <= rglob    ) ? __uint_as_float(tf32_bits(p1)) : 0.f;
                    p2 = (colb     <= rglob + 8) ? __uint_as_float(tf32_bits(p2)) : 0.f;
                    p3 = (colb + 1 <= rglob + 8) ? __uint_as_float(tf32_bits(p3)) : 0.f;
                    float* pp = smf + OPs + pcol * PF + prow;
                    pp[0]      = p0;
                    pp[PF]     = p1;
                    pp[8]      = p2;
                    pp[PF + 8] = p3;
                }
            }
        }
        __syncthreads();

        // ---- O += P V (and l += P·1 via ones-column mma) ----
        #pragma unroll
        for (int ks = 0; ks < 8; ks++) {
            uint32_t a[2][4];
            #pragma unroll
            for (int mi = 0; mi < 2; mi++) {
                const float* pp = smf + OPs + (ks*8 + tg) * PF + (r2*32 + mi*16 + g);
                a[mi][0] = __float_as_uint(pp[0]);
                a[mi][1] = __float_as_uint(pp[8]);
                a[mi][2] = __float_as_uint(pp[4*PF]);
                a[mi][3] = __float_as_uint(pp[4*PF + 8]);
            }
            #pragma unroll
            for (int nj = 0; nj < 8; nj++) {
                const float* vv = smf + OVs + (ks*8 + tg) * VF + (c2*64 + nj*8 + g);
                uint32_t b0 = __float_as_uint(vv[0]);
                uint32_t b1 = __float_as_uint(vv[4*VF]);
                mma_tf32(oacc[0][nj], a[0][0],a[0][1],a[0][2],a[0][3], b0, b1);
                mma_tf32(oacc[1][nj], a[1][0],a[1][1],a[1][2],a[1][3], b0, b1);
            }
            uint32_t bo = (g == 0) ? 0x3F800000u : 0u;   // ones column -> row sums
            mma_tf32(lacc[0], a[0][0],a[0][1],a[0][2],a[0][3], bo, bo);
            mma_tf32(lacc[1], a[1][0],a[1][1],a[1][2],a[1][3], bo, bo);
        }
    }

    // ---- epilogue: broadcast l within quads, scale, store ----
    {
        float* Og = Og_ + ((size_t)b * SEQ + (size_t)qt * BR) * DIM;
        #pragma unroll
        for (int mi = 0; mi < 2; mi++) {
            float l0 = __shfl_sync(0xffffffffu, lacc[mi][0], lane & 28);  // row g
            float l1 = __shfl_sync(0xffffffffu, lacc[mi][2], lane & 28);  // row g+8
            float i0 = 1.0f / l0, i1 = 1.0f / l1;
            const int row = r2*32 + mi*16 + g;
            #pragma unroll
            for (int nj = 0; nj < 8; nj++) {
                const int col = c2*64 + nj*8 + 2*tg;
                float2 v0 = make_float2(oacc[mi][nj][0] * i0, oacc[mi][nj][1] * i0);
                float2 v1 = make_float2(oacc[mi][nj][2] * i1, oacc[mi][nj][3] * i1);
                *(float2*)(Og + (size_t)row       * DIM + col) = v0;
                *(float2*)(Og + (size_t)(row + 8) * DIM + col) = v1;
            }
        }
    }
}

extern "C" void kernel_launch(void* const* d_in, const int* in_sizes, int n_in,
                              void* d_out, int out_size)
{
    const float* Q = (const float*)d_in[0];
    const float* K = (const float*)d_in[1];
    const float* V = (const float*)d_in[2];
    float* O = (float*)d_out;

    cudaFuncSetAttribute(fa_mma_kernel,
                         cudaFuncAttributeMaxDynamicSharedMemorySize, SMEM_BYTES);
    fa_mma_kernel<<<256, NTHR, SMEM_BYTES>>>(Q, K, V, O);
}